// round 8
// baseline (speedup 1.0000x reference)
#include <cuda_runtime.h>
#include <cstdint>

// Constants from reference: softcap 30, z-loss 1e-4, smoothing 0.1, ignore -100.
#define N_MAX  8192
#define CHUNKS 4

// Per-(chunk,row) scratch (device globals: no allocation allowed).
__device__ float g_pe[CHUNKS][N_MAX];   // partial sum(exp(s))
__device__ float g_ps[CHUNKS][N_MAX];   // partial sum(s)
__device__ float g_st[N_MAX];           // softcapped target logit (written by owning chunk)
__device__ int   g_valid[N_MAX];

static __device__ __forceinline__ float tanh_fast(float a) {
    float r;
    asm("tanh.approx.f32 %0, %1;" : "=f"(r) : "f"(a));
    return r;
}

// grid = (CHUNKS, N). Each CTA streams one V/CHUNKS slice of one row:
// s = 30*tanh(x/30); accumulates sum(s), sum(exp(s)). No max-shift needed:
// s in (-30,30) so exp(s) <= 1e13 and a full-row sum <= 5.4e17 (fp32-safe).
__global__ void __launch_bounds__(256) ce_row_kernel(
    const float* __restrict__ logits,
    const int* __restrict__ target,
    int V)
{
    const int chunk = blockIdx.x;
    const int row   = blockIdx.y;
    const int tid   = threadIdx.x;

    const int W     = (V + CHUNKS - 1) / CHUNKS;
    const int start = chunk * W;
    const int end   = min(start + W, V);

    const float* rp  = logits + (size_t)row * (size_t)V;
    const float* cp  = rp + start;
    const int    len = end - start;

    float sum_e = 0.f;
    float sum_s = 0.f;

    // Alignment prologue for float4 (chunk starts are not 16B-aligned in general).
    int pre = (int)(((16u - (unsigned)((uintptr_t)cp & 15u)) & 15u) >> 2);
    if (pre > len) pre = len;

    for (int i = tid; i < pre; i += 256) {
        float s = 30.0f * tanh_fast(cp[i] * (1.0f / 30.0f));
        sum_s += s;
        sum_e += __expf(s);
    }

    const float4* cp4 = reinterpret_cast<const float4*>(cp + pre);
    const int n4 = (len - pre) >> 2;

    #pragma unroll 4
    for (int j = tid; j < n4; j += 256) {
        float4 v = __ldcs(cp4 + j);   // read-once stream: evict-first
        float s0 = 30.0f * tanh_fast(v.x * (1.0f / 30.0f));
        float s1 = 30.0f * tanh_fast(v.y * (1.0f / 30.0f));
        float s2 = 30.0f * tanh_fast(v.z * (1.0f / 30.0f));
        float s3 = 30.0f * tanh_fast(v.w * (1.0f / 30.0f));
        sum_s += (s0 + s1) + (s2 + s3);
        sum_e += (__expf(s0) + __expf(s1)) + (__expf(s2) + __expf(s3));
    }

    for (int i = pre + (n4 << 2) + tid; i < len; i += 256) {
        float s = 30.0f * tanh_fast(cp[i] * (1.0f / 30.0f));
        sum_s += s;
        sum_e += __expf(s);
    }

    // Block reduction: warp shuffle then cross-warp via smem.
    #pragma unroll
    for (int o = 16; o > 0; o >>= 1) {
        sum_e += __shfl_xor_sync(0xffffffffu, sum_e, o);
        sum_s += __shfl_xor_sync(0xffffffffu, sum_s, o);
    }
    __shared__ float sh_e[8];
    __shared__ float sh_s[8];
    const int warp = tid >> 5;
    const int lane = tid & 31;
    if (lane == 0) { sh_e[warp] = sum_e; sh_s[warp] = sum_s; }
    __syncthreads();

    if (tid == 0) {
        float e = 0.f, ss = 0.f;
        #pragma unroll
        for (int w = 0; w < 8; w++) { e += sh_e[w]; ss += sh_s[w]; }
        g_pe[chunk][row] = e;
        g_ps[chunk][row] = ss;

        const int tgt = target[row];
        if (chunk == 0) g_valid[row] = (tgt >= 0 && tgt < V) ? 1 : 0;
        if (tgt >= start && tgt < end) {   // exactly one chunk owns the target
            g_st[row] = 30.0f * tanh_fast(rp[tgt] * (1.0f / 30.0f));
        }
    }
}

// Combine chunk partials + per-row loss math + deterministic mean -> [loss, z_loss].
__global__ void __launch_bounds__(1024) ce_reduce_kernel(float* __restrict__ out, int N, int V)
{
    const int tid = threadIdx.x;
    float l = 0.f, z = 0.f;
    int v = 0;

    for (int row = tid; row < N; row += 1024) {
        float e  = 0.f, ss = 0.f;
        #pragma unroll
        for (int c = 0; c < CHUNKS; c++) { e += g_pe[c][row]; ss += g_ps[c][row]; }
        if (g_valid[row]) {
            float lse    = __logf(e);
            float ce     = lse - g_st[row];
            float smooth = lse - ss / (float)V;
            float zi     = 1e-4f * lse * lse;
            l += 0.9f * ce + 0.1f * smooth + zi;
            z += zi;
            v += 1;
        }
    }

    #pragma unroll
    for (int o = 16; o > 0; o >>= 1) {
        l += __shfl_xor_sync(0xffffffffu, l, o);
        z += __shfl_xor_sync(0xffffffffu, z, o);
        v += __shfl_xor_sync(0xffffffffu, v, o);
    }
    __shared__ float shl[32];
    __shared__ float shz[32];
    __shared__ int   shv[32];
    const int warp = tid >> 5;
    const int lane = tid & 31;
    if (lane == 0) { shl[warp] = l; shz[warp] = z; shv[warp] = v; }
    __syncthreads();
    if (tid == 0) {
        float L = 0.f, Z = 0.f;
        int   C = 0;
        #pragma unroll
        for (int w = 0; w < 32; w++) { L += shl[w]; Z += shz[w]; C += shv[w]; }
        float nv = (float)(C > 0 ? C : 1);
        out[0] = L / nv;
        out[1] = Z / nv;
    }
}

extern "C" void kernel_launch(void* const* d_in, const int* in_sizes, int n_in,
                              void* d_out, int out_size) {
    const float* logits = (const float*)d_in[0];
    const int*   target = (const int*)d_in[1];
    const int N = in_sizes[1];
    const int V = in_sizes[0] / N;

    dim3 grid(CHUNKS, N);
    ce_row_kernel<<<grid, 256>>>(logits, target, V);
    ce_reduce_kernel<<<1, 1024>>>((float*)d_out, N, V);
}

// round 9
// speedup vs baseline: 1.0229x; 1.0229x over previous
#include <cuda_runtime.h>
#include <cstdint>

// Constants from reference: softcap 30, z-loss 1e-4, smoothing 0.1, ignore -100.
#define N_MAX  8192
#define CHUNKS 4

// Per-(chunk,row) scratch (device globals: no allocation allowed).
__device__ float g_pe[CHUNKS][N_MAX];   // partial sum(exp(s))
__device__ float g_ps[CHUNKS][N_MAX];   // partial sum(s)
__device__ float g_st[N_MAX];           // softcapped target logit (written by owning chunk)
__device__ int   g_valid[N_MAX];

static __device__ __forceinline__ float tanh_fast(float a) {
    float r;
    asm("tanh.approx.f32 %0, %1;" : "=f"(r) : "f"(a));
    return r;
}

// grid = (CHUNKS, N). Each CTA streams one V/CHUNKS slice of one row:
// s = 30*tanh(x/30); accumulates sum(s), sum(exp(s)). No max-shift needed:
// s in (-30,30) so exp(s) <= 1e13 and a full-row sum <= 5.4e17 (fp32-safe).
__global__ void __launch_bounds__(256) ce_row_kernel(
    const float* __restrict__ logits,
    const int* __restrict__ target,
    int V)
{
    const int chunk = blockIdx.x;
    const int row   = blockIdx.y;
    const int tid   = threadIdx.x;

    const int W     = (V + CHUNKS - 1) / CHUNKS;
    const int start = chunk * W;
    const int end   = min(start + W, V);

    const float* rp  = logits + (size_t)row * (size_t)V;
    const float* cp  = rp + start;
    const int    len = end - start;

    float sum_e = 0.f;
    float sum_s = 0.f;

    // Alignment prologue for float4 (chunk starts are not 16B-aligned in general).
    int pre = (int)(((16u - (unsigned)((uintptr_t)cp & 15u)) & 15u) >> 2);
    if (pre > len) pre = len;

    for (int i = tid; i < pre; i += 256) {
        float s = 30.0f * tanh_fast(cp[i] * (1.0f / 30.0f));
        sum_s += s;
        sum_e += __expf(s);
    }

    const float4* cp4 = reinterpret_cast<const float4*>(cp + pre);
    const int n4 = (len - pre) >> 2;

    #pragma unroll 4
    for (int j = tid; j < n4; j += 256) {
        float4 v = __ldcs(cp4 + j);   // read-once stream: evict-first
        float s0 = 30.0f * tanh_fast(v.x * (1.0f / 30.0f));
        float s1 = 30.0f * tanh_fast(v.y * (1.0f / 30.0f));
        float s2 = 30.0f * tanh_fast(v.z * (1.0f / 30.0f));
        float s3 = 30.0f * tanh_fast(v.w * (1.0f / 30.0f));
        sum_s += (s0 + s1) + (s2 + s3);
        sum_e += (__expf(s0) + __expf(s1)) + (__expf(s2) + __expf(s3));
    }

    for (int i = pre + (n4 << 2) + tid; i < len; i += 256) {
        float s = 30.0f * tanh_fast(cp[i] * (1.0f / 30.0f));
        sum_s += s;
        sum_e += __expf(s);
    }

    // Block reduction: warp shuffle then cross-warp via smem.
    #pragma unroll
    for (int o = 16; o > 0; o >>= 1) {
        sum_e += __shfl_xor_sync(0xffffffffu, sum_e, o);
        sum_s += __shfl_xor_sync(0xffffffffu, sum_s, o);
    }
    __shared__ float sh_e[8];
    __shared__ float sh_s[8];
    const int warp = tid >> 5;
    const int lane = tid & 31;
    if (lane == 0) { sh_e[warp] = sum_e; sh_s[warp] = sum_s; }
    __syncthreads();

    if (tid == 0) {
        float e = 0.f, ss = 0.f;
        #pragma unroll
        for (int w = 0; w < 8; w++) { e += sh_e[w]; ss += sh_s[w]; }
        g_pe[chunk][row] = e;
        g_ps[chunk][row] = ss;

        const int tgt = target[row];
        if (chunk == 0) g_valid[row] = (tgt >= 0 && tgt < V) ? 1 : 0;
        if (tgt >= start && tgt < end) {   // exactly one chunk owns the target
            g_st[row] = 30.0f * tanh_fast(rp[tgt] * (1.0f / 30.0f));
        }
    }
}

// Combine chunk partials + per-row loss math + deterministic mean -> [loss, z_loss].
__global__ void __launch_bounds__(1024) ce_reduce_kernel(float* __restrict__ out, int N, int V)
{
    const int tid = threadIdx.x;
    float l = 0.f, z = 0.f;
    int v = 0;

    for (int row = tid; row < N; row += 1024) {
        float e  = 0.f, ss = 0.f;
        #pragma unroll
        for (int c = 0; c < CHUNKS; c++) { e += g_pe[c][row]; ss += g_ps[c][row]; }
        if (g_valid[row]) {
            float lse    = __logf(e);
            float ce     = lse - g_st[row];
            float smooth = lse - ss / (float)V;
            float zi     = 1e-4f * lse * lse;
            l += 0.9f * ce + 0.1f * smooth + zi;
            z += zi;
            v += 1;
        }
    }

    #pragma unroll
    for (int o = 16; o > 0; o >>= 1) {
        l += __shfl_xor_sync(0xffffffffu, l, o);
        z += __shfl_xor_sync(0xffffffffu, z, o);
        v += __shfl_xor_sync(0xffffffffu, v, o);
    }
    __shared__ float shl[32];
    __shared__ float shz[32];
    __shared__ int   shv[32];
    const int warp = tid >> 5;
    const int lane = tid & 31;
    if (lane == 0) { shl[warp] = l; shz[warp] = z; shv[warp] = v; }
    __syncthreads();
    if (tid == 0) {
        float L = 0.f, Z = 0.f;
        int   C = 0;
        #pragma unroll
        for (int w = 0; w < 32; w++) { L += shl[w]; Z += shz[w]; C += shv[w]; }
        float nv = (float)(C > 0 ? C : 1);
        out[0] = L / nv;
        out[1] = Z / nv;
    }
}

extern "C" void kernel_launch(void* const* d_in, const int* in_sizes, int n_in,
                              void* d_out, int out_size) {
    const float* logits = (const float*)d_in[0];
    const int*   target = (const int*)d_in[1];
    const int N = in_sizes[1];
    const int V = in_sizes[0] / N;

    dim3 grid(CHUNKS, N);
    ce_row_kernel<<<grid, 256>>>(logits, target, V);
    ce_reduce_kernel<<<1, 1024>>>((float*)d_out, N, V);
}